// round 13
// baseline (speedup 1.0000x reference)
#include <cuda_runtime.h>
#include <math.h>

// NPSLoss via cp.async.bulk (TMA 1D) + 3-stage smem pipeline.
// Envelope trick for the 20-color codebook distance (validated R3-R12).
// Each block owns a CONTIGUOUS chunk of stages; each stage = 1024 pixels
// = 3 x 4KB bulk copies (r,g,b planes) -> large sequential DRAM runs,
// no L1 fill path, 36KB in flight per CTA.

#define HW_SHIFT 18            // 512*512
#define HW (1 << HW_SHIFT)
#define STAGE_PX 1024
#define STAGE_PLANE_BYTES 4096
#define STAGE_BYTES 12288
#define NBUF 3

__device__ __forceinline__ unsigned smem_u32(const void* p) {
    unsigned a;
    asm("{ .reg .u64 t; cvta.to.shared.u64 t, %1; cvt.u32.u64 %0, t; }"
        : "=r"(a) : "l"(p));
    return a;
}

__device__ __forceinline__ void mbar_init(unsigned mb, unsigned cnt) {
    asm volatile("mbarrier.init.shared.b64 [%0], %1;" :: "r"(mb), "r"(cnt) : "memory");
}
__device__ __forceinline__ void mbar_expect_tx(unsigned mb, unsigned bytes) {
    asm volatile("mbarrier.arrive.expect_tx.shared.b64 _, [%0], %1;"
                 :: "r"(mb), "r"(bytes) : "memory");
}
__device__ __forceinline__ void bulk_g2s(unsigned dst, const void* src,
                                         unsigned bytes, unsigned mb) {
    asm volatile("cp.async.bulk.shared::cluster.global.mbarrier::complete_tx::bytes "
                 "[%0], [%1], %2, [%3];"
                 :: "r"(dst), "l"(src), "r"(bytes), "r"(mb) : "memory");
}
__device__ __forceinline__ void mbar_wait(unsigned mb, unsigned phase) {
    asm volatile(
        "{\n\t"
        ".reg .pred P;\n\t"
        "WL_%=:\n\t"
        "mbarrier.try_wait.parity.acquire.cta.shared::cta.b64 P, [%0], %1, 0x989680;\n\t"
        "@P bra.uni WD_%=;\n\t"
        "bra.uni WL_%=;\n\t"
        "WD_%=:\n\t"
        "}"
        :: "r"(mb), "r"(phase) : "memory");
}

__device__ __forceinline__ float pix_dist(float r, float g, float b) {
    float rgb  = (r + g) + b;
    float vmax = fmaxf(fmaxf(r, g), b);
    float vmin = fminf(fminf(r, g), b);
    float smax = rgb - vmin;
    float pp   = fmaf(r, r, fmaf(g, g, b * b));

    float m1 = fminf(0.25f - vmax, fmaf(-1.5f, vmax, 0.5625f));
    m1 = fminf(m1, fmaf(-2.0f, vmax, 1.0f));
    float m2 = fminf(0.5f - smax, fmaf(-2.0f, smax, 2.0f));
    float m3 = fminf(fmaf(-0.5f, rgb, 0.1875f), 0.75f - rgb);
    m3 = fminf(m3, fminf(fmaf(-1.5f, rgb, 1.6875f), fmaf(-2.0f, rgb, 3.0f)));

    float m  = fminf(fminf(m1, m2), m3);
    float d2 = fminf(pp + m, pp);
    float y;
    asm("sqrt.approx.f32 %0, %1;" : "=f"(y) : "f"(fabsf(d2)));
    return y;
}

__global__ void nps_zero_kernel(float* out) {
    if (threadIdx.x == 0 && blockIdx.x == 0) out[0] = 0.0f;
}

__global__ void __launch_bounds__(256) nps_loss_kernel(
    const float* __restrict__ x, float* __restrict__ out,
    int n_stages, float inv_n)
{
    __shared__ __align__(16) float buf[NBUF][3 * STAGE_PX];   // 36KB
    __shared__ __align__(8)  unsigned long long mbar[NBUF];

    int tid = threadIdx.x;

    // Contiguous per-block stage chunk (big sequential DRAM runs per block).
    int nb    = gridDim.x;
    int per   = n_stages / nb;
    int rem   = n_stages % nb;
    int bid   = blockIdx.x;
    int start = bid * per + min(bid, rem);
    int count = per + (bid < rem ? 1 : 0);

    unsigned mb_u32[NBUF];
    #pragma unroll
    for (int i = 0; i < NBUF; i++) mb_u32[i] = smem_u32(&mbar[i]);

    if (tid == 0) {
        #pragma unroll
        for (int i = 0; i < NBUF; i++) mbar_init(mb_u32[i], 1);
    }
    __syncthreads();

    // Prologue: fill up to NBUF stages.
    if (tid == 0) {
        int pro = count < NBUF ? count : NBUF;
        for (int s = 0; s < pro; s++) {
            int p0  = (start + s) * STAGE_PX;
            int img = p0 >> HW_SHIFT;
            int off = p0 & (HW - 1);
            const float* src = x + (size_t)img * (3 * HW) + off;
            unsigned dst = smem_u32(&buf[s][0]);
            mbar_expect_tx(mb_u32[s], STAGE_BYTES);
            bulk_g2s(dst,                           src,          STAGE_PLANE_BYTES, mb_u32[s]);
            bulk_g2s(dst + STAGE_PLANE_BYTES,       src + HW,     STAGE_PLANE_BYTES, mb_u32[s]);
            bulk_g2s(dst + 2 * STAGE_PLANE_BYTES,   src + 2 * HW, STAGE_PLANE_BYTES, mb_u32[s]);
        }
    }

    float acc = 0.0f;
    for (int s = 0; s < count; s++) {
        int b  = s % NBUF;
        int ph = (s / NBUF) & 1;
        mbar_wait(mb_u32[b], ph);

        const float4* rr = (const float4*)&buf[b][0];
        const float4* gg = (const float4*)&buf[b][STAGE_PX];
        const float4* bb = (const float4*)&buf[b][2 * STAGE_PX];
        float4 r4 = rr[tid], g4 = gg[tid], b4 = bb[tid];
        float d0 = pix_dist(r4.x, g4.x, b4.x);
        float d1 = pix_dist(r4.y, g4.y, b4.y);
        float d2 = pix_dist(r4.z, g4.z, b4.z);
        float d3 = pix_dist(r4.w, g4.w, b4.w);
        acc += (d0 + d1) + (d2 + d3);

        __syncthreads();                 // all threads done reading buffer b
        if (tid == 0 && s + NBUF < count) {
            int sn  = s + NBUF;
            int p0  = (start + sn) * STAGE_PX;
            int img = p0 >> HW_SHIFT;
            int off = p0 & (HW - 1);
            const float* src = x + (size_t)img * (3 * HW) + off;
            unsigned dst = smem_u32(&buf[b][0]);
            mbar_expect_tx(mb_u32[b], STAGE_BYTES);
            bulk_g2s(dst,                         src,          STAGE_PLANE_BYTES, mb_u32[b]);
            bulk_g2s(dst + STAGE_PLANE_BYTES,     src + HW,     STAGE_PLANE_BYTES, mb_u32[b]);
            bulk_g2s(dst + 2 * STAGE_PLANE_BYTES, src + 2 * HW, STAGE_PLANE_BYTES, mb_u32[b]);
        }
    }

    // warp reduction
    #pragma unroll
    for (int sh = 16; sh > 0; sh >>= 1)
        acc += __shfl_xor_sync(0xFFFFFFFFu, acc, sh);

    __shared__ float warp_sums[8];
    int lane = tid & 31;
    int wid  = tid >> 5;
    if (lane == 0) warp_sums[wid] = acc;
    __syncthreads();

    if (wid == 0) {
        float v = (lane < 8) ? warp_sums[lane] : 0.0f;
        #pragma unroll
        for (int sh = 4; sh > 0; sh >>= 1)
            v += __shfl_xor_sync(0xFFFFFFFFu, v, sh);
        if (lane == 0) atomicAdd(out, v * inv_n);
    }
}

extern "C" void kernel_launch(void* const* d_in, const int* in_sizes, int n_in,
                              void* d_out, int out_size)
{
    const float* x = (const float*)d_in[0];
    float* out = (float*)d_out;

    int n_elems  = in_sizes[0];              // B*3*H*W
    int n_pixels = n_elems / 3;              // 8388608
    int n_stages = n_pixels / STAGE_PX;      // 8192
    float inv_n  = 1.0f / (float)n_pixels;

    nps_zero_kernel<<<1, 32>>>(out);

    const int threads = 256;
    int blocks = 888;                        // 148 SMs x 6 CTAs (36KB smem each)
    if (blocks > n_stages) blocks = n_stages;
    nps_loss_kernel<<<blocks, threads>>>(x, out, n_stages, inv_n);
}

// round 14
// speedup vs baseline: 1.1345x; 1.1345x over previous
#include <cuda_runtime.h>
#include <math.h>

// NPSLoss: mean over pixels of sqrt(min_k ||p - c_k||^2), 20-color fixed codebook.
// Envelope trick: all non-black scores s_k = |c_k|^2 - 2 p.c_k are decreasing
// affine in one of {max(r,g,b), rgb - min(r,g,b), rgb}; black gives d2 = |p|^2.
//
// R14 = R9 champion loop with DEFAULT L2 eviction policy (no evict_last).
// evict_last pins ~100MB into protected L2 ways (> capacity) -> possible
// replacement pathology; R12 showed no replay-residency upside. This isolates
// the eviction-policy axis, the only one never tested alone.

#define HW_SHIFT 18            // 512*512
#define HW (1 << HW_SHIFT)

struct f8 { float v[8]; };

__device__ __forceinline__ f8 ldg_el8(const float* p) {
    unsigned a0, a1, a2, a3, a4, a5, a6, a7;
    asm("ld.global.nc.v8.b32 {%0,%1,%2,%3,%4,%5,%6,%7}, [%8];"
        : "=r"(a0), "=r"(a1), "=r"(a2), "=r"(a3),
          "=r"(a4), "=r"(a5), "=r"(a6), "=r"(a7)
        : "l"(p));
    f8 o;
    o.v[0] = __uint_as_float(a0); o.v[1] = __uint_as_float(a1);
    o.v[2] = __uint_as_float(a2); o.v[3] = __uint_as_float(a3);
    o.v[4] = __uint_as_float(a4); o.v[5] = __uint_as_float(a5);
    o.v[6] = __uint_as_float(a6); o.v[7] = __uint_as_float(a7);
    return o;
}

__device__ __forceinline__ float pix_dist(float r, float g, float b) {
    float rgb  = (r + g) + b;
    float vmax = fmaxf(fmaxf(r, g), b);
    float vmin = fminf(fminf(r, g), b);
    float smax = rgb - vmin;                       // max of the pair sums
    float pp   = fmaf(r, r, fmaf(g, g, b * b));

    float m1 = fminf(0.25f - vmax, fmaf(-1.5f, vmax, 0.5625f));
    m1 = fminf(m1, fmaf(-2.0f, vmax, 1.0f));
    float m2 = fminf(0.5f - smax, fmaf(-2.0f, smax, 2.0f));
    float m3 = fminf(fmaf(-0.5f, rgb, 0.1875f), 0.75f - rgb);
    m3 = fminf(m3, fminf(fmaf(-1.5f, rgb, 1.6875f), fmaf(-2.0f, rgb, 3.0f)));

    float m  = fminf(fminf(m1, m2), m3);
    float d2 = fminf(pp + m, pp);                  // black: s = 0
    float y;
    asm("sqrt.approx.f32 %0, %1;" : "=f"(y) : "f"(fabsf(d2)));
    return y;
}

__global__ void nps_zero_kernel(float* out) {
    if (threadIdx.x == 0 && blockIdx.x == 0) out[0] = 0.0f;
}

__global__ void __launch_bounds__(256) nps_loss_kernel(
    const float* __restrict__ x, float* __restrict__ out,
    int n_pairs, float inv_n)
{
    float acc = 0.0f;
    const int stride = gridDim.x * blockDim.x;
    for (int pi = blockIdx.x * blockDim.x + threadIdx.x; pi < n_pairs; pi += stride) {
        int p   = pi << 3;                 // 8 pixels per iteration
        int img = p >> HW_SHIFT;
        int off = p & (HW - 1);
        const float* base = x + (size_t)img * (3 * HW) + off;
        // 3 front-batched 32B loads
        f8 r = ldg_el8(base);
        f8 g = ldg_el8(base + HW);
        f8 b = ldg_el8(base + 2 * HW);

        float d0 = pix_dist(r.v[0], g.v[0], b.v[0]);
        float d1 = pix_dist(r.v[1], g.v[1], b.v[1]);
        float d2 = pix_dist(r.v[2], g.v[2], b.v[2]);
        float d3 = pix_dist(r.v[3], g.v[3], b.v[3]);
        float d4 = pix_dist(r.v[4], g.v[4], b.v[4]);
        float d5 = pix_dist(r.v[5], g.v[5], b.v[5]);
        float d6 = pix_dist(r.v[6], g.v[6], b.v[6]);
        float d7 = pix_dist(r.v[7], g.v[7], b.v[7]);
        acc += ((d0 + d1) + (d2 + d3)) + ((d4 + d5) + (d6 + d7));
    }

    // warp reduction
    #pragma unroll
    for (int sh = 16; sh > 0; sh >>= 1)
        acc += __shfl_xor_sync(0xFFFFFFFFu, acc, sh);

    __shared__ float warp_sums[8];
    int lane = threadIdx.x & 31;
    int wid  = threadIdx.x >> 5;
    if (lane == 0) warp_sums[wid] = acc;
    __syncthreads();

    if (wid == 0) {
        float v = (lane < (blockDim.x >> 5)) ? warp_sums[lane] : 0.0f;
        #pragma unroll
        for (int sh = 4; sh > 0; sh >>= 1)
            v += __shfl_xor_sync(0xFFFFFFFFu, v, sh);
        if (lane == 0) atomicAdd(out, v * inv_n);
    }
}

extern "C" void kernel_launch(void* const* d_in, const int* in_sizes, int n_in,
                              void* d_out, int out_size)
{
    const float* x = (const float*)d_in[0];
    float* out = (float*)d_out;

    int n_elems  = in_sizes[0];          // B*3*H*W
    int n_pixels = n_elems / 3;          // 8388608
    int n_pairs  = n_pixels >> 3;        // 8 pixels per iteration
    float inv_n  = 1.0f / (float)n_pixels;

    nps_zero_kernel<<<1, 32>>>(out);

    const int threads = 256;
    int blocks = (n_pairs + threads - 1) / threads;
    const int max_blocks = 148 * 8;      // 1184, champion grid
    if (blocks > max_blocks) blocks = max_blocks;
    nps_loss_kernel<<<blocks, threads>>>(x, out, n_pairs, inv_n);
}

// round 15
// speedup vs baseline: 1.1366x; 1.0019x over previous
#include <cuda_runtime.h>
#include <math.h>

// NPSLoss: mean over pixels of sqrt(min_k ||p - c_k||^2), 20-color fixed codebook.
// d2_k = |p|^2 + s_k,  s_k = |c_k|^2 - 2 p.c_k.  All non-black s_k are DECREASING
// affine functions of one of:
//   vmax = max(r,g,b)          (9 single-channel colors -> 3 lines)
//   smax = rgb - min(r,g,b)    (6 two-channel colors    -> 2 lines)
//   rgb  = r+g+b               (4 gray colors           -> 4 lines)
// Black (0,0,0): s = 0 -> d2 candidate = |p|^2.
//
// FINAL (= R9 champion, 16.864us, reproduced twice): grid-stride 1184 blocks
// (148 SMs x 8 queued CTAs), 3 front-batched evict_last 32B loads, pairwise
// tree accumulation, approx sqrt, zero-kernel + atomicAdd epilogue.
// Converged: 10 structural variants (occupancy, MLP, epilogue, L2 policy,
// TMA bulk path) all land in 16.86-17.15us or regress -> memory-system limit.

#define HW_SHIFT 18            // 512*512
#define HW (1 << HW_SHIFT)

struct f8 { float v[8]; };

__device__ __forceinline__ f8 ldg_el8(const float* p) {
    unsigned a0, a1, a2, a3, a4, a5, a6, a7;
    asm("ld.global.nc.L2::evict_last.v8.b32 {%0,%1,%2,%3,%4,%5,%6,%7}, [%8];"
        : "=r"(a0), "=r"(a1), "=r"(a2), "=r"(a3),
          "=r"(a4), "=r"(a5), "=r"(a6), "=r"(a7)
        : "l"(p));
    f8 o;
    o.v[0] = __uint_as_float(a0); o.v[1] = __uint_as_float(a1);
    o.v[2] = __uint_as_float(a2); o.v[3] = __uint_as_float(a3);
    o.v[4] = __uint_as_float(a4); o.v[5] = __uint_as_float(a5);
    o.v[6] = __uint_as_float(a6); o.v[7] = __uint_as_float(a7);
    return o;
}

__device__ __forceinline__ float pix_dist(float r, float g, float b) {
    float rgb  = (r + g) + b;
    float vmax = fmaxf(fmaxf(r, g), b);
    float vmin = fminf(fminf(r, g), b);
    float smax = rgb - vmin;                       // max of the pair sums
    float pp   = fmaf(r, r, fmaf(g, g, b * b));

    // single-channel colors c in {0.5, 0.75, 1}, evaluated at vmax
    float m1 = fminf(0.25f - vmax, fmaf(-1.5f, vmax, 0.5625f));
    m1 = fminf(m1, fmaf(-2.0f, vmax, 1.0f));
    // pair colors c in {0.5, 1}, evaluated at smax
    float m2 = fminf(0.5f - smax, fmaf(-2.0f, smax, 2.0f));
    // grays c in {0.25, 0.5, 0.75, 1}, evaluated at rgb
    float m3 = fminf(fmaf(-0.5f, rgb, 0.1875f), 0.75f - rgb);
    m3 = fminf(m3, fminf(fmaf(-1.5f, rgb, 1.6875f), fmaf(-2.0f, rgb, 3.0f)));

    float m  = fminf(fminf(m1, m2), m3);
    float d2 = fminf(pp + m, pp);                  // black color: s = 0
    float y;
    asm("sqrt.approx.f32 %0, %1;" : "=f"(y) : "f"(fabsf(d2)));
    return y;
}

__global__ void nps_zero_kernel(float* out) {
    if (threadIdx.x == 0 && blockIdx.x == 0) out[0] = 0.0f;
}

__global__ void __launch_bounds__(256) nps_loss_kernel(
    const float* __restrict__ x, float* __restrict__ out,
    int n_pairs, float inv_n)
{
    float acc = 0.0f;
    const int stride = gridDim.x * blockDim.x;
    for (int pi = blockIdx.x * blockDim.x + threadIdx.x; pi < n_pairs; pi += stride) {
        int p   = pi << 3;                 // 8 pixels per iteration
        int img = p >> HW_SHIFT;
        int off = p & (HW - 1);
        const float* base = x + (size_t)img * (3 * HW) + off;
        // 3 front-batched 32B loads -> high MLP, low issue pressure
        f8 r = ldg_el8(base);
        f8 g = ldg_el8(base + HW);
        f8 b = ldg_el8(base + 2 * HW);

        float d0 = pix_dist(r.v[0], g.v[0], b.v[0]);
        float d1 = pix_dist(r.v[1], g.v[1], b.v[1]);
        float d2 = pix_dist(r.v[2], g.v[2], b.v[2]);
        float d3 = pix_dist(r.v[3], g.v[3], b.v[3]);
        float d4 = pix_dist(r.v[4], g.v[4], b.v[4]);
        float d5 = pix_dist(r.v[5], g.v[5], b.v[5]);
        float d6 = pix_dist(r.v[6], g.v[6], b.v[6]);
        float d7 = pix_dist(r.v[7], g.v[7], b.v[7]);
        // pairwise tree: serial-chain depth 3 instead of 8
        acc += ((d0 + d1) + (d2 + d3)) + ((d4 + d5) + (d6 + d7));
    }

    // warp reduction
    #pragma unroll
    for (int sh = 16; sh > 0; sh >>= 1)
        acc += __shfl_xor_sync(0xFFFFFFFFu, acc, sh);

    __shared__ float warp_sums[8];
    int lane = threadIdx.x & 31;
    int wid  = threadIdx.x >> 5;
    if (lane == 0) warp_sums[wid] = acc;
    __syncthreads();

    if (wid == 0) {
        float v = (lane < (blockDim.x >> 5)) ? warp_sums[lane] : 0.0f;
        #pragma unroll
        for (int sh = 4; sh > 0; sh >>= 1)
            v += __shfl_xor_sync(0xFFFFFFFFu, v, sh);
        if (lane == 0) atomicAdd(out, v * inv_n);
    }
}

extern "C" void kernel_launch(void* const* d_in, const int* in_sizes, int n_in,
                              void* d_out, int out_size)
{
    const float* x = (const float*)d_in[0];
    float* out = (float*)d_out;

    int n_elems  = in_sizes[0];          // B*3*H*W
    int n_pixels = n_elems / 3;          // 8388608
    int n_pairs  = n_pixels >> 3;        // 8 pixels per iteration
    float inv_n  = 1.0f / (float)n_pixels;

    nps_zero_kernel<<<1, 32>>>(out);

    const int threads = 256;
    int blocks = (n_pairs + threads - 1) / threads;
    const int max_blocks = 148 * 8;      // 1184: champion grid
    if (blocks > max_blocks) blocks = max_blocks;
    nps_loss_kernel<<<blocks, threads>>>(x, out, n_pairs, inv_n);
}